// round 6
// baseline (speedup 1.0000x reference)
#include <cuda_runtime.h>

#define Dh 128
#define NHEAD 16
#define NB 2
#define SEQ 2048
#define NHD (NHEAD*Dh)
#define MROWS (NB*SEQ)

__device__ float g_QKV[3][(size_t)NB*NHEAD*SEQ*Dh];
__device__ float g_CTX[(size_t)NB*NHEAD*SEQ*Dh];
__device__ float g_LINV[(size_t)NB*NHEAD*SEQ];

#define LDA 132     // Q/K tile ld
#define LDW 68      // w tile ld
#define LDV 136     // V tile ld

// smem layout (u32 units)
#define OFF_Q   0
#define OFF_KB0 16896            // 128*132
#define OFF_KB1 (16896 + 8704)
#define OFF_VB0 (16896 + 2*8704)
#define OFF_VB1 (16896 + 3*8704)
#define SMEM_ATTN ((16896 + 4*8704) * 4)   // 206848 B

__device__ __forceinline__ unsigned f2tf32(float f){
    unsigned r; asm("cvt.rna.tf32.f32 %0, %1;" : "=r"(r) : "f"(f)); return r;
}
__device__ __forceinline__ void mma8(float* d, const unsigned* a, unsigned b0, unsigned b1){
    asm volatile("mma.sync.aligned.m16n8k8.row.col.f32.tf32.tf32.f32 "
        "{%0,%1,%2,%3},{%4,%5,%6,%7},{%8,%9},{%0,%1,%2,%3};"
        : "+f"(d[0]), "+f"(d[1]), "+f"(d[2]), "+f"(d[3])
        : "r"(a[0]), "r"(a[1]), "r"(a[2]), "r"(a[3]), "r"(b0), "r"(b1));
}
__device__ __forceinline__ unsigned smem_u32(const void* p){
    unsigned a;
    asm("{ .reg .u64 t; cvta.to.shared.u64 t, %1; cvt.u32.u64 %0, t; }" : "=r"(a) : "l"(p));
    return a;
}
__device__ __forceinline__ void cpa16(unsigned s, const void* g){
    asm volatile("cp.async.ca.shared.global [%0], [%1], 16;" :: "r"(s), "l"(g));
}

// 128x128 f32 -> smem tf32 (RNA), row-major ld=LDA, scaled; NT = thread count
template<int NT>
__device__ __forceinline__ void load_tile(unsigned* dst, const float* src, int srcStride,
                                          float scale, int tid){
    #pragma unroll
    for (int it = 0; it < 4096/NT; ++it){
        int idx = tid + it*NT;
        int r = idx >> 5, c = (idx & 31) << 2;
        float4 v = *(const float4*)(src + (size_t)r*srcStride + c);
        uint4 u = make_uint4(f2tf32(v.x*scale), f2tf32(v.y*scale),
                             f2tf32(v.z*scale), f2tf32(v.w*scale));
        *(uint4*)(dst + r*LDA + c) = u;
    }
}

// warp GEMM 128x128x128 (A ld=LDA [m][k], B ld=LDA [n][k]) for projections
__device__ __forceinline__ void wgemm(float acc[2][8][4], const unsigned* As, const unsigned* Bs,
                                      int m0w, int n0w, int g, int t4){
    #pragma unroll 4
    for (int kk = 0; kk < 16; ++kk){
        unsigned a[2][4];
        #pragma unroll
        for (int mi = 0; mi < 2; ++mi){
            const unsigned* p = As + (m0w + mi*16 + g)*LDA + kk*8 + t4;
            a[mi][0] = p[0];       a[mi][2] = p[4];
            a[mi][1] = p[8*LDA];   a[mi][3] = p[8*LDA + 4];
        }
        #pragma unroll
        for (int j = 0; j < 8; ++j){
            const unsigned* p = Bs + (n0w + j*8 + g)*LDA + kk*8 + t4;
            unsigned b0 = p[0], b1 = p[4];
            mma8(acc[0][j], a[0], b0, b1);
            mma8(acc[1][j], a[1], b0, b1);
        }
    }
}

// ---------------- QKV projection; K,V outputs pre-rounded to tf32 ----------------
__global__ __launch_bounds__(256) void proj_tc(const float* __restrict__ X,
                                               const float* __restrict__ W,
                                               const float* __restrict__ bias, int which)
{
    extern __shared__ unsigned sm[];
    unsigned* As = sm;
    unsigned* Bs = sm + 128*LDA;
    const int tid = threadIdx.x, lane = tid & 31, g = lane >> 2, t4 = lane & 3, w = tid >> 5;
    const int m0w = (w & 3) * 32, n0w = (w >> 2) * 64;
    const int m0 = blockIdx.y * 128, n0 = blockIdx.x * 128;

    load_tile<256>(As, X + (size_t)m0*Dh, Dh, 1.f, tid);
    load_tile<256>(Bs, W + (size_t)n0*Dh, Dh, 1.f, tid);
    __syncthreads();

    float acc[2][8][4] = {};
    wgemm(acc, As, Bs, m0w, n0w, g, t4);

    const int b = m0 >> 11, sbase = m0 & 2047, h = n0 >> 7;
    float* Yb = g_QKV[which] + ((size_t)(b*NHEAD + h)*SEQ)*Dh;
    #pragma unroll
    for (int mi = 0; mi < 2; ++mi)
        #pragma unroll
        for (int half = 0; half < 2; ++half){
            int rl = m0w + mi*16 + half*8 + g;
            float* Yr = Yb + (size_t)(sbase + rl)*Dh;
            #pragma unroll
            for (int j = 0; j < 8; ++j){
                int d = n0w + j*8 + 2*t4;
                float v0 = acc[mi][j][half*2]   + bias[n0 + d];
                float v1 = acc[mi][j][half*2+1] + bias[n0 + d + 1];
                if (which != 0){      // K,V: pre-round to tf32-representable f32
                    v0 = __uint_as_float(f2tf32(v0));
                    v1 = __uint_as_float(f2tf32(v1));
                }
                *(float2*)(Yr + d) = make_float2(v0, v1);
            }
        }
}

// ---------------- single-pass fused attention, 512 threads ----------------
__global__ __launch_bounds__(512, 1) void attn_mma(const int* __restrict__ mask,
                                                   float* __restrict__ weights)
{
    extern __shared__ unsigned sm[];
    unsigned* Qs = sm + OFF_Q;
    __shared__ float lpart[128][2];
    __shared__ float linvs[128];

    const int tid = threadIdx.x, lane = tid & 31, g = lane >> 2, t4 = lane & 3, w = tid >> 5;
    const int m0w = (w & 7) * 16;      // 8 m-warps x 16 rows
    const int wn  = w >> 3;            // 2 n-warps
    const int n0s = wn * 32;           // QK n-offset
    const int n0d = wn * 64;           // PV n-offset
    const int h = blockIdx.x, q0 = blockIdx.y * 128, b = blockIdx.z;
    const size_t bh = (size_t)(b*NHEAD + h);
    const float* Qg = g_QKV[0] + bh*SEQ*Dh + (size_t)q0*Dh;
    const float* Kg = g_QKV[1] + bh*SEQ*Dh;
    const float* Vg = g_QKV[2] + bh*SEQ*Dh;
    const int*   mb = mask + (size_t)b*SEQ*SEQ;
    float*       wb = weights + bh*(size_t)SEQ*SEQ;

    const unsigned smbase = smem_u32(sm);
    const unsigned kb_u[2] = { smbase + OFF_KB0*4u, smbase + OFF_KB1*4u };
    const unsigned vb_u[2] = { smbase + OFF_VB0*4u, smbase + OFF_VB1*4u };

    // prologue: stream K0,V0 (pre-rounded f32), load Q (RNA tf32, pre-scaled)
    #pragma unroll
    for (int it2 = 0; it2 < 4; ++it2){
        int idx = tid + it2*512;
        int r = idx >> 5, c = (idx & 31) << 2;
        cpa16(kb_u[0] + (unsigned)(r*LDA + c)*4u, Kg + (size_t)r*Dh + c);
        cpa16(vb_u[0] + (unsigned)(r*LDV + c)*4u, Vg + (size_t)r*Dh + c);
    }
    asm volatile("cp.async.commit_group;");
    load_tile<512>(Qs, Qg, Dh, 0.08838834764831845f, tid);

    float lsum[2] = {0.f, 0.f};
    float ctx[8][4] = {};

    for (int it = 0; it < 32; ++it){
        const int t0 = it * 64;
        const int cur = it & 1, nxt = cur ^ 1;
        if (it + 1 < 32){
            const float* Kn = Kg + (size_t)(t0 + 64)*Dh;
            const float* Vn = Vg + (size_t)(t0 + 64)*Dh;
            #pragma unroll
            for (int it2 = 0; it2 < 4; ++it2){
                int idx = tid + it2*512;
                int r = idx >> 5, c = (idx & 31) << 2;
                cpa16(kb_u[nxt] + (unsigned)(r*LDA + c)*4u, Kn + (size_t)r*Dh + c);
                cpa16(vb_u[nxt] + (unsigned)(r*LDV + c)*4u, Vn + (size_t)r*Dh + c);
            }
        }
        asm volatile("cp.async.commit_group;");
        asm volatile("cp.async.wait_group 1;");
        __syncthreads();

        const unsigned* Ks = sm + (cur ? OFF_KB1 : OFF_KB0);
        const unsigned* Vs = sm + (cur ? OFF_VB1 : OFF_VB0);
        unsigned*       Ws = sm + (cur ? OFF_KB1 : OFF_KB0);

        // ---- QK: warp tile 16x32, acc[4][4] ----
        float acc[4][4] = {};
        #pragma unroll 4
        for (int kk = 0; kk < 16; ++kk){
            unsigned a[4];
            {
                const unsigned* p = Qs + (m0w + g)*LDA + kk*8 + t4;
                a[0] = p[0];       a[2] = p[4];
                a[1] = p[8*LDA];   a[3] = p[8*LDA + 4];
            }
            #pragma unroll
            for (int j = 0; j < 4; ++j){
                const unsigned* p = Ks + (n0s + j*8 + g)*LDA + kk*8 + t4;
                mma8(acc[j], a, p[0], p[4]);   // K already tf32-rounded
            }
        }
        __syncthreads();    // K reads done -> buffer reusable as w tile

        // ---- epilogue: u = exp(s + mask*-1e9); STG u; STS u; lsum ----
        {
            const int rl0 = m0w + g;
            const int r0  = q0 + rl0;
            const int* mr0 = mb + (size_t)r0*SEQ + t0;
            const int* mr1 = mr0 + 8*SEQ;
            float* wr0 = wb + (size_t)r0*SEQ + t0;
            float* wr1 = wr0 + 8*SEQ;
            #pragma unroll
            for (int j = 0; j < 4; ++j){
                int cc = n0s + j*8 + 2*t4;
                int2 mA = *(const int2*)(mr0 + cc);
                int2 mB = *(const int2*)(mr1 + cc);
                float u00 = __expf(fmaf((float)mA.x, -1e9f, acc[j][0]));
                float u01 = __expf(fmaf((float)mA.y, -1e9f, acc[j][1]));
                float u10 = __expf(fmaf((float)mB.x, -1e9f, acc[j][2]));
                float u11 = __expf(fmaf((float)mB.y, -1e9f, acc[j][3]));
                *(float2*)(wr0 + cc) = make_float2(u00, u01);
                *(float2*)(wr1 + cc) = make_float2(u10, u11);
                lsum[0] += u00 + u01;
                lsum[1] += u10 + u11;
                *(uint2*)(Ws + rl0*LDW + cc)       = make_uint2(__float_as_uint(u00), __float_as_uint(u01));
                *(uint2*)(Ws + (rl0 + 8)*LDW + cc) = make_uint2(__float_as_uint(u10), __float_as_uint(u11));
            }
        }
        __syncthreads();    // w tile visible (V already resident)

        // ---- PV: ctx += w(128x64, ld=LDW) * V(64x128, ld=LDV) ----
        #pragma unroll 4
        for (int kk = 0; kk < 8; ++kk){
            unsigned a[4];
            {
                const unsigned* p = Ws + (m0w + g)*LDW + kk*8 + t4;
                a[0] = p[0];       a[2] = p[4];
                a[1] = p[8*LDW];   a[3] = p[8*LDW + 4];
            }
            #pragma unroll
            for (int j = 0; j < 8; ++j){
                const unsigned* p = Vs + (kk*8 + t4)*LDV + n0d + j*8 + g;
                mma8(ctx[j], a, p[0], p[4*LDV]);
            }
        }
        __syncthreads();    // PV done -> buffers free for next cp.async
    }

    // ---- reduce l across quad lanes + two n-warps ----
    #pragma unroll
    for (int half = 0; half < 2; ++half){
        float v = lsum[half];
        v += __shfl_xor_sync(0xffffffffu, v, 1);
        v += __shfl_xor_sync(0xffffffffu, v, 2);
        if (t4 == 0) lpart[m0w + half*8 + g][wn] = v;
    }
    __syncthreads();
    if (tid < 128){
        float li = 1.0f / (lpart[tid][0] + lpart[tid][1]);
        linvs[tid] = li;
        g_LINV[bh*SEQ + q0 + tid] = li;
    }
    __syncthreads();

    // ---- ctx * linv -> g_CTX ----
    float* Cb = g_CTX + (bh*SEQ + (size_t)q0)*Dh;
    #pragma unroll
    for (int half = 0; half < 2; ++half){
        int rl = m0w + half*8 + g;
        float li = linvs[rl];
        #pragma unroll
        for (int j = 0; j < 8; ++j){
            int d = n0d + j*8 + 2*t4;
            *(float2*)(Cb + (size_t)rl*Dh + d) =
                make_float2(ctx[j][half*2]*li, ctx[j][half*2+1]*li);
        }
    }
}

// ---------------- weights row-normalize: w *= linv[row] ----------------
__global__ __launch_bounds__(256) void norm_w(float* __restrict__ weights)
{
    const float li = g_LINV[blockIdx.x];
    float4* row = (float4*)(weights + (size_t)blockIdx.x * SEQ);
    int t = threadIdx.x;
    float4 a = row[t], c = row[t + 256];
    a.x*=li; a.y*=li; a.z*=li; a.w*=li;
    c.x*=li; c.y*=li; c.z*=li; c.w*=li;
    row[t] = a; row[t + 256] = c;
}

// ---------------- output projection (tf32 mma) ----------------
__global__ __launch_bounds__(256) void outproj_tc(const float* __restrict__ Wd,
                                                  const float* __restrict__ bd,
                                                  float* __restrict__ out)
{
    extern __shared__ unsigned sm[];
    unsigned* As = sm;
    unsigned* Bs = sm + 128*LDA;
    const int tid = threadIdx.x, lane = tid & 31, g = lane >> 2, t4 = lane & 3, w = tid >> 5;
    const int m0w = (w & 3) * 32, n0w = (w >> 2) * 64;
    const int m0 = blockIdx.y * 128;
    const int b = m0 >> 11, sbase = m0 & 2047;

    float acc[2][8][4] = {};
    for (int kt = 0; kt < NHEAD; ++kt){
        __syncthreads();
        load_tile<256>(As, g_CTX + (((size_t)(b*NHEAD + kt))*SEQ + sbase)*Dh, Dh, 1.f, tid);
        load_tile<256>(Bs, Wd + (size_t)kt*Dh, NHD, 1.f, tid);
        __syncthreads();
        wgemm(acc, As, Bs, m0w, n0w, g, t4);
    }
    #pragma unroll
    for (int mi = 0; mi < 2; ++mi)
        #pragma unroll
        for (int half = 0; half < 2; ++half){
            int rl = m0w + mi*16 + half*8 + g;
            float* Or = out + (size_t)(m0 + rl)*Dh;
            #pragma unroll
            for (int j = 0; j < 8; ++j){
                int d = n0w + j*8 + 2*t4;
                *(float2*)(Or + d) = make_float2(acc[mi][j][half*2]   + bd[d],
                                                 acc[mi][j][half*2+1] + bd[d + 1]);
            }
        }
}

// ---------------------------------------------------------------------------
extern "C" void kernel_launch(void* const* d_in, const int* in_sizes, int n_in,
                              void* d_out, int out_size)
{
    (void)in_sizes; (void)n_in; (void)out_size;
    const float* x    = (const float*)d_in[0];
    const int*   mask = (const int*)  d_in[1];
    const float* Wq   = (const float*)d_in[2];
    const float* bq   = (const float*)d_in[3];
    const float* Wk   = (const float*)d_in[4];
    const float* bk   = (const float*)d_in[5];
    const float* Wv   = (const float*)d_in[6];
    const float* bv   = (const float*)d_in[7];
    const float* Wd   = (const float*)d_in[8];
    const float* bd   = (const float*)d_in[9];

    float* out     = (float*)d_out;
    float* weights = out + (size_t)NB*SEQ*Dh;

    const size_t smem_proj = (size_t)2*128*LDA*4;     // 135168
    const size_t smem_attn = SMEM_ATTN;               // 206848

    cudaFuncSetAttribute(proj_tc,    cudaFuncAttributeMaxDynamicSharedMemorySize, (int)smem_proj);
    cudaFuncSetAttribute(attn_mma,   cudaFuncAttributeMaxDynamicSharedMemorySize, (int)smem_attn);
    cudaFuncSetAttribute(outproj_tc, cudaFuncAttributeMaxDynamicSharedMemorySize, (int)smem_proj);

    dim3 g1(NHD/128, MROWS/128);            // (16, 32)
    proj_tc<<<g1, 256, smem_proj>>>(x, Wq, bq, 0);
    proj_tc<<<g1, 256, smem_proj>>>(x, Wk, bk, 1);
    proj_tc<<<g1, 256, smem_proj>>>(x, Wv, bv, 2);

    dim3 g2(NHEAD, SEQ/128, NB);            // (16, 16, 2)
    attn_mma<<<g2, 512, smem_attn>>>(mask, weights);

    norm_w<<<NB*NHEAD*SEQ, 256>>>(weights);

    dim3 g3(1, MROWS/128);
    outproj_tc<<<g3, 256, smem_proj>>>(Wd, bd, out);
}

// round 7
// speedup vs baseline: 1.1967x; 1.1967x over previous
#include <cuda_runtime.h>

#define Dh 128
#define NHEAD 16
#define NB 2
#define SEQ 2048
#define NHD (NHEAD*Dh)
#define MROWS (NB*SEQ)

__device__ float g_QKV[3][(size_t)NB*NHEAD*SEQ*Dh];
__device__ float g_CTX[(size_t)NB*NHEAD*SEQ*Dh];
__device__ float g_LINV[(size_t)NB*NHEAD*SEQ];
__device__ unsigned g_MBITS[(size_t)NB*SEQ*(SEQ/32)];

#define LDA 132     // Q/K/B tile ld
#define LDW 68      // w tile ld
#define LDV 136     // V tile ld

// attn smem (u32 units): Q 64x132, K 64x132 (aliased by w), V 64x136
#define OFF_K 8448
#define OFF_V (8448 + 8448)
#define SMEM_ATTN ((8448 + 8448 + 8704) * 4)   // 102400 B

__device__ __forceinline__ unsigned f2tf32(float f){
    unsigned r; asm("cvt.rna.tf32.f32 %0, %1;" : "=r"(r) : "f"(f)); return r;
}
__device__ __forceinline__ float ex2f(float x){
    float r; asm("ex2.approx.f32 %0, %1;" : "=f"(r) : "f"(x)); return r;
}
__device__ __forceinline__ void mma8(float* d, const unsigned* a, unsigned b0, unsigned b1){
    asm volatile("mma.sync.aligned.m16n8k8.row.col.f32.tf32.tf32.f32 "
        "{%0,%1,%2,%3},{%4,%5,%6,%7},{%8,%9},{%0,%1,%2,%3};"
        : "+f"(d[0]), "+f"(d[1]), "+f"(d[2]), "+f"(d[3])
        : "r"(a[0]), "r"(a[1]), "r"(a[2]), "r"(a[3]), "r"(b0), "r"(b1));
}
__device__ __forceinline__ unsigned smem_u32(const void* p){
    unsigned a;
    asm("{ .reg .u64 t; cvta.to.shared.u64 t, %1; cvt.u32.u64 %0, t; }" : "=r"(a) : "l"(p));
    return a;
}
__device__ __forceinline__ void cpa16(unsigned s, const void* g){
    asm volatile("cp.async.ca.shared.global [%0], [%1], 16;" :: "r"(s), "l"(g));
}

// ROWSx128 f32 -> smem tf32 (RNA), row-major ld=LDA, scaled
template<int NT, int ROWS>
__device__ __forceinline__ void load_tile(unsigned* dst, const float* src, int srcStride,
                                          float scale, int tid){
    #pragma unroll
    for (int it = 0; it < ROWS*32/NT; ++it){
        int idx = tid + it*NT;
        int r = idx >> 5, c = (idx & 31) << 2;
        float4 v = *(const float4*)(src + (size_t)r*srcStride + c);
        uint4 u = make_uint4(f2tf32(v.x*scale), f2tf32(v.y*scale),
                             f2tf32(v.z*scale), f2tf32(v.w*scale));
        *(uint4*)(dst + r*LDA + c) = u;
    }
}

// ---------------- mask -> bitmask ----------------
__global__ __launch_bounds__(256) void prep_mask(const int* __restrict__ mask)
{
    size_t o = (size_t)blockIdx.x * 256 + threadIdx.x;   // one uint32 per thread
    const int* p = mask + o*32;
    unsigned bits = 0;
    #pragma unroll
    for (int i = 0; i < 32; i += 4){
        int4 v = *(const int4*)(p + i);
        bits |= ((unsigned)(v.x & 1) << i)     | ((unsigned)(v.y & 1) << (i+1))
              | ((unsigned)(v.z & 1) << (i+2)) | ((unsigned)(v.w & 1) << (i+3));
    }
    g_MBITS[o] = bits;
}

// ---------------- QKV projection; K,V pre-rounded to tf32 ----------------
__global__ __launch_bounds__(256) void proj_tc(const float* __restrict__ X,
                                               const float* __restrict__ W,
                                               const float* __restrict__ bias, int which)
{
    extern __shared__ unsigned sm[];
    unsigned* As = sm;
    unsigned* Bs = sm + 128*LDA;
    const int tid = threadIdx.x, lane = tid & 31, g = lane >> 2, t4 = lane & 3, w = tid >> 5;
    const int m0w = (w & 3) * 32, n0w = (w >> 2) * 64;
    const int m0 = blockIdx.y * 128, n0 = blockIdx.x * 128;

    load_tile<256,128>(As, X + (size_t)m0*Dh, Dh, 1.f, tid);
    load_tile<256,128>(Bs, W + (size_t)n0*Dh, Dh, 1.f, tid);
    __syncthreads();

    float acc[2][8][4] = {};
    #pragma unroll 4
    for (int kk = 0; kk < 16; ++kk){
        unsigned a[2][4];
        #pragma unroll
        for (int mi = 0; mi < 2; ++mi){
            const unsigned* p = As + (m0w + mi*16 + g)*LDA + kk*8 + t4;
            a[mi][0] = p[0];       a[mi][2] = p[4];
            a[mi][1] = p[8*LDA];   a[mi][3] = p[8*LDA + 4];
        }
        #pragma unroll
        for (int j = 0; j < 8; ++j){
            const unsigned* p = Bs + (n0w + j*8 + g)*LDA + kk*8 + t4;
            mma8(acc[0][j], a[0], p[0], p[4]);
            mma8(acc[1][j], a[1], p[0], p[4]);
        }
    }

    const int b = m0 >> 11, sbase = m0 & 2047, h = n0 >> 7;
    float* Yb = g_QKV[which] + ((size_t)(b*NHEAD + h)*SEQ)*Dh;
    #pragma unroll
    for (int mi = 0; mi < 2; ++mi)
        #pragma unroll
        for (int half = 0; half < 2; ++half){
            int rl = m0w + mi*16 + half*8 + g;
            float* Yr = Yb + (size_t)(sbase + rl)*Dh;
            #pragma unroll
            for (int j = 0; j < 8; ++j){
                int d = n0w + j*8 + 2*t4;
                float v0 = acc[mi][j][half*2]   + bias[n0 + d];
                float v1 = acc[mi][j][half*2+1] + bias[n0 + d + 1];
                if (which != 0){
                    v0 = __uint_as_float(f2tf32(v0));
                    v1 = __uint_as_float(f2tf32(v1));
                }
                *(float2*)(Yr + d) = make_float2(v0, v1);
            }
        }
}

// ---------------- fused attention: 64 q-rows/CTA, 128 thr, 2 CTAs/SM ----------------
__global__ __launch_bounds__(128, 2) void attn_mma(float* __restrict__ weights)
{
    extern __shared__ unsigned sm[];
    unsigned* Qs = sm;
    unsigned* Ks = sm + OFF_K;       // aliased as w tile after QK
    unsigned* Vs = sm + OFF_V;
    __shared__ float lpart[64][2];
    __shared__ float linvs[64];

    const int tid = threadIdx.x, lane = tid & 31, g = lane >> 2, t4 = lane & 3, w = tid >> 5;
    const int m0w = (w & 1) * 32;        // 2 m-warps x 32 rows
    const int wn  = w >> 1;              // 2 n-warps
    const int n0s = wn * 32;             // QK n-offset within 64-key tile
    const int n0d = wn * 64;             // PV d-offset
    const int h = blockIdx.x, q0 = blockIdx.y * 64, b = blockIdx.z;
    const size_t bh = (size_t)(b*NHEAD + h);
    const float* Qg = g_QKV[0] + bh*SEQ*Dh + (size_t)q0*Dh;
    const float* Kg = g_QKV[1] + bh*SEQ*Dh;
    const float* Vg = g_QKV[2] + bh*SEQ*Dh;
    const unsigned* mbits = g_MBITS + (size_t)b*SEQ*(SEQ/32);
    float* wb = weights + bh*(size_t)SEQ*SEQ;

    const unsigned kb = smem_u32(Ks), vb = smem_u32(Vs);

    // prologue: cp K0,V0 (pre-rounded f32); Q with scale/sqrt(D)*log2(e)
    #pragma unroll
    for (int i = 0; i < 16; ++i){
        int idx = tid + i*128;
        int r = idx >> 5, c = (idx & 31) << 2;
        cpa16(kb + (unsigned)(r*LDA + c)*4u, Kg + (size_t)r*Dh + c);
        cpa16(vb + (unsigned)(r*LDV + c)*4u, Vg + (size_t)r*Dh + c);
    }
    asm volatile("cp.async.commit_group;");
    load_tile<128,64>(Qs, Qg, Dh, 0.12751744532f, tid);   // (1/sqrt(128))*log2(e)

    float lsum[2][2] = {{0.f,0.f},{0.f,0.f}};
    float ctx[2][8][4] = {};

    for (int it = 0; it < 32; ++it){
        const int t0 = it * 64;
        asm volatile("cp.async.wait_group 0;");
        __syncthreads();

        // ---- QK: warp 32x32, acc[2][4][4] ----
        float acc[2][4][4] = {};
        #pragma unroll 4
        for (int kk = 0; kk < 16; ++kk){
            unsigned a[2][4];
            #pragma unroll
            for (int mi = 0; mi < 2; ++mi){
                const unsigned* p = Qs + (m0w + mi*16 + g)*LDA + kk*8 + t4;
                a[mi][0] = p[0];       a[mi][2] = p[4];
                a[mi][1] = p[8*LDA];   a[mi][3] = p[8*LDA + 4];
            }
            #pragma unroll
            for (int j = 0; j < 4; ++j){
                const unsigned* p = Ks + (n0s + j*8 + g)*LDA + kk*8 + t4;
                mma8(acc[0][j], a[0], p[0], p[4]);
                mma8(acc[1][j], a[1], p[0], p[4]);
            }
        }
        __syncthreads();    // K reads done -> reuse as w tile

        // ---- epilogue: u = masked ? 0 : ex2(s); STG u; STS u; lsum ----
        unsigned* Ws = Ks;
        #pragma unroll
        for (int mi = 0; mi < 2; ++mi){
            const int rl0 = m0w + mi*16 + g;
            const int r0  = q0 + rl0;
            const int wword = (t0 + n0s) >> 5;
            const unsigned mb0 = mbits[(size_t)r0*(SEQ/32) + wword];
            const unsigned mb1 = mbits[(size_t)(r0+8)*(SEQ/32) + wword];
            float* wr0 = wb + (size_t)r0*SEQ + t0;
            float* wr1 = wr0 + 8*SEQ;
            #pragma unroll
            for (int j = 0; j < 4; ++j){
                int cc = n0s + j*8 + 2*t4;
                int sh = j*8 + 2*t4;
                float f00 = ex2f(acc[mi][j][0]);
                float f01 = ex2f(acc[mi][j][1]);
                float f10 = ex2f(acc[mi][j][2]);
                float f11 = ex2f(acc[mi][j][3]);
                float u00 = ((mb0 >> sh) & 1u)     ? 0.f : f00;
                float u01 = ((mb0 >> (sh+1)) & 1u) ? 0.f : f01;
                float u10 = ((mb1 >> sh) & 1u)     ? 0.f : f10;
                float u11 = ((mb1 >> (sh+1)) & 1u) ? 0.f : f11;
                *(float2*)(wr0 + cc) = make_float2(u00, u01);
                *(float2*)(wr1 + cc) = make_float2(u10, u11);
                lsum[mi][0] += u00 + u01;
                lsum[mi][1] += u10 + u11;
                *(uint2*)(Ws + rl0*LDW + cc)       = make_uint2(__float_as_uint(u00), __float_as_uint(u01));
                *(uint2*)(Ws + (rl0 + 8)*LDW + cc) = make_uint2(__float_as_uint(u10), __float_as_uint(u11));
            }
        }
        __syncthreads();    // w tile visible

        // ---- PV: ctx += w(64x64, ld=LDW) * V(64x128, ld=LDV) ----
        #pragma unroll 4
        for (int kk = 0; kk < 8; ++kk){
            unsigned a[2][4];
            #pragma unroll
            for (int mi = 0; mi < 2; ++mi){
                const unsigned* p = Ws + (m0w + mi*16 + g)*LDW + kk*8 + t4;
                a[mi][0] = p[0];       a[mi][2] = p[4];
                a[mi][1] = p[8*LDW];   a[mi][3] = p[8*LDW + 4];
            }
            #pragma unroll
            for (int j = 0; j < 8; ++j){
                const unsigned* p = Vs + (kk*8 + t4)*LDV + n0d + j*8 + g;
                mma8(ctx[0][j], a[0], p[0], p[4*LDV]);
                mma8(ctx[1][j], a[1], p[0], p[4*LDV]);
            }
        }
        __syncthreads();    // PV done -> K/V buffers free

        if (it + 1 < 32){
            const float* Kn = Kg + (size_t)(t0 + 64)*Dh;
            const float* Vn = Vg + (size_t)(t0 + 64)*Dh;
            #pragma unroll
            for (int i = 0; i < 16; ++i){
                int idx = tid + i*128;
                int r = idx >> 5, c = (idx & 31) << 2;
                cpa16(kb + (unsigned)(r*LDA + c)*4u, Kn + (size_t)r*Dh + c);
                cpa16(vb + (unsigned)(r*LDV + c)*4u, Vn + (size_t)r*Dh + c);
            }
        }
        asm volatile("cp.async.commit_group;");
    }

    // ---- reduce l (quad lanes, then the 2 n-warps) ----
    #pragma unroll
    for (int mi = 0; mi < 2; ++mi)
        #pragma unroll
        for (int half = 0; half < 2; ++half){
            float v = lsum[mi][half];
            v += __shfl_xor_sync(0xffffffffu, v, 1);
            v += __shfl_xor_sync(0xffffffffu, v, 2);
            if (t4 == 0) lpart[m0w + mi*16 + half*8 + g][wn] = v;
        }
    __syncthreads();
    if (tid < 64){
        float li = 1.0f / (lpart[tid][0] + lpart[tid][1]);
        linvs[tid] = li;
        g_LINV[bh*SEQ + q0 + tid] = li;
    }
    __syncthreads();

    // ---- ctx * linv -> g_CTX ----
    float* Cb = g_CTX + (bh*SEQ + (size_t)q0)*Dh;
    #pragma unroll
    for (int mi = 0; mi < 2; ++mi)
        #pragma unroll
        for (int half = 0; half < 2; ++half){
            int rl = m0w + mi*16 + half*8 + g;
            float li = linvs[rl];
            #pragma unroll
            for (int j = 0; j < 8; ++j){
                int d = n0d + j*8 + 2*t4;
                *(float2*)(Cb + (size_t)rl*Dh + d) =
                    make_float2(ctx[mi][j][half*2]*li, ctx[mi][j][half*2+1]*li);
            }
        }
}

// ---------------- weights row-normalize ----------------
__global__ __launch_bounds__(256) void norm_w(float* __restrict__ weights)
{
    const float li = g_LINV[blockIdx.x];
    float4* row = (float4*)(weights + (size_t)blockIdx.x * SEQ);
    int t = threadIdx.x;
    float4 a = row[t], c = row[t + 256];
    a.x*=li; a.y*=li; a.z*=li; a.w*=li;
    c.x*=li; c.y*=li; c.z*=li; c.w*=li;
    row[t] = a; row[t + 256] = c;
}

// ---------------- output projection: 64-row m-tiles ----------------
__global__ __launch_bounds__(256) void outproj_tc(const float* __restrict__ Wd,
                                                  const float* __restrict__ bd,
                                                  float* __restrict__ out)
{
    extern __shared__ unsigned sm[];
    unsigned* As = sm;              // 64 x LDA
    unsigned* Bs = sm + 64*LDA;     // 128 x LDA
    const int tid = threadIdx.x, lane = tid & 31, g = lane >> 2, t4 = lane & 3, w = tid >> 5;
    const int m0w = (w & 3) * 16, n0w = (w >> 2) * 64;
    const int m0 = blockIdx.x * 64;
    const int b = m0 >> 11, sbase = m0 & 2047;

    float acc[8][4] = {};
    for (int kt = 0; kt < NHEAD; ++kt){
        __syncthreads();
        load_tile<256,64>(As, g_CTX + (((size_t)(b*NHEAD + kt))*SEQ + sbase)*Dh, Dh, 1.f, tid);
        load_tile<256,128>(Bs, Wd + (size_t)kt*Dh, NHD, 1.f, tid);
        __syncthreads();
        #pragma unroll 4
        for (int kk = 0; kk < 16; ++kk){
            unsigned a[4];
            const unsigned* pa = As + (m0w + g)*LDA + kk*8 + t4;
            a[0] = pa[0];       a[2] = pa[4];
            a[1] = pa[8*LDA];   a[3] = pa[8*LDA + 4];
            #pragma unroll
            for (int j = 0; j < 8; ++j){
                const unsigned* p = Bs + (n0w + j*8 + g)*LDA + kk*8 + t4;
                mma8(acc[j], a, p[0], p[4]);
            }
        }
    }
    #pragma unroll
    for (int half = 0; half < 2; ++half){
        int rl = m0w + half*8 + g;
        float* Or = out + (size_t)(m0 + rl)*Dh;
        #pragma unroll
        for (int j = 0; j < 8; ++j){
            int d = n0w + j*8 + 2*t4;
            *(float2*)(Or + d) = make_float2(acc[j][half*2]   + bd[d],
                                             acc[j][half*2+1] + bd[d + 1]);
        }
    }
}

// ---------------------------------------------------------------------------
extern "C" void kernel_launch(void* const* d_in, const int* in_sizes, int n_in,
                              void* d_out, int out_size)
{
    (void)in_sizes; (void)n_in; (void)out_size;
    const float* x    = (const float*)d_in[0];
    const int*   mask = (const int*)  d_in[1];
    const float* Wq   = (const float*)d_in[2];
    const float* bq   = (const float*)d_in[3];
    const float* Wk   = (const float*)d_in[4];
    const float* bk   = (const float*)d_in[5];
    const float* Wv   = (const float*)d_in[6];
    const float* bv   = (const float*)d_in[7];
    const float* Wd   = (const float*)d_in[8];
    const float* bd   = (const float*)d_in[9];

    float* out     = (float*)d_out;
    float* weights = out + (size_t)NB*SEQ*Dh;

    const size_t smem_proj = (size_t)2*128*LDA*4;          // 135168
    const size_t smem_attn = SMEM_ATTN;                    // 102400
    const size_t smem_outp = (size_t)(64*LDA + 128*LDA)*4; // 101376

    cudaFuncSetAttribute(proj_tc,    cudaFuncAttributeMaxDynamicSharedMemorySize, (int)smem_proj);
    cudaFuncSetAttribute(attn_mma,   cudaFuncAttributeMaxDynamicSharedMemorySize, (int)smem_attn);
    cudaFuncSetAttribute(outproj_tc, cudaFuncAttributeMaxDynamicSharedMemorySize, (int)smem_outp);

    prep_mask<<<NB*SEQ*(SEQ/32)/256, 256>>>(mask);

    dim3 g1(NHD/128, MROWS/128);            // (16, 32)
    proj_tc<<<g1, 256, smem_proj>>>(x, Wq, bq, 0);
    proj_tc<<<g1, 256, smem_proj>>>(x, Wk, bk, 1);
    proj_tc<<<g1, 256, smem_proj>>>(x, Wv, bv, 2);

    dim3 g2(NHEAD, SEQ/64, NB);             // (16, 32, 2) = 1024 CTAs, 2/SM
    attn_mma<<<g2, 128, smem_attn>>>(weights);

    norm_w<<<NB*NHEAD*SEQ, 256>>>(weights);

    outproj_tc<<<MROWS/64, 256, smem_outp>>>(Wd, bd, out);
}

// round 9
// speedup vs baseline: 1.5917x; 1.3301x over previous
#include <cuda_runtime.h>
#include <cuda_fp16.h>

#define Dh 128
#define NHEAD 16
#define NB 2
#define SEQ 2048
#define NHD (NHEAD*Dh)
#define MROWS (NB*SEQ)

__device__ __half g_Qh[(size_t)NB*NHEAD*SEQ*Dh];    // (B,H,S,D), pre-scaled
__device__ __half g_Kh[(size_t)NB*NHEAD*SEQ*Dh];    // (B,H,S,D)
__device__ __half g_VTh[(size_t)NB*NHEAD*SEQ*Dh];   // (B,H,D,S)
__device__ float  g_CTX[(size_t)NB*NHEAD*SEQ*Dh];
__device__ float  g_LINV[(size_t)NB*NHEAD*SEQ];
__device__ unsigned g_MBITS[(size_t)NB*SEQ*(SEQ/32)];

#define LDA 132                 // fp32 tile ld (projections)
// attn smem word offsets (halves stored 2-per-word)
#define LQW 68                  // Q/K row stride in words (136 halves)
#define LVW 36                  // V^T / w row stride in words (72 halves)
#define OFF_KB0 4352            // Q = 64*68 words
#define OFF_KB1 (4352 + 4352)
#define OFF_VB0 (4352 + 2*4352)
#define OFF_VB1 (4352 + 2*4352 + 4608)
#define SMEM_ATTN ((4352 + 2*4352 + 2*4608) * 4)    // 89088 B

#define QSCALE 0.12751744532f   // (1/sqrt(128)) * log2(e)

__device__ __forceinline__ unsigned f2tf32(float f){
    unsigned r; asm("cvt.rna.tf32.f32 %0, %1;" : "=r"(r) : "f"(f)); return r;
}
__device__ __forceinline__ float ex2f(float x){
    float r; asm("ex2.approx.f32 %0, %1;" : "=f"(r) : "f"(x)); return r;
}
// pack two f32 -> one f16x2 word (lo = a, hi = b)
__device__ __forceinline__ unsigned pack_h2(float a, float b){
    unsigned r; asm("cvt.rn.f16x2.f32 %0, %2, %1;" : "=r"(r) : "f"(a), "f"(b)); return r;
}
// tf32 m16n8k8 (projections)
__device__ __forceinline__ void mma8(float* d, const unsigned* a, unsigned b0, unsigned b1){
    asm volatile("mma.sync.aligned.m16n8k8.row.col.f32.tf32.tf32.f32 "
        "{%0,%1,%2,%3},{%4,%5,%6,%7},{%8,%9},{%0,%1,%2,%3};"
        : "+f"(d[0]), "+f"(d[1]), "+f"(d[2]), "+f"(d[3])
        : "r"(a[0]), "r"(a[1]), "r"(a[2]), "r"(a[3]), "r"(b0), "r"(b1));
}
// fp16 m16n8k16 (attention)
__device__ __forceinline__ void mma16h(float* d, const unsigned* a, unsigned b0, unsigned b1){
    asm volatile("mma.sync.aligned.m16n8k16.row.col.f32.f16.f16.f32 "
        "{%0,%1,%2,%3},{%4,%5,%6,%7},{%8,%9},{%0,%1,%2,%3};"
        : "+f"(d[0]), "+f"(d[1]), "+f"(d[2]), "+f"(d[3])
        : "r"(a[0]), "r"(a[1]), "r"(a[2]), "r"(a[3]), "r"(b0), "r"(b1));
}
__device__ __forceinline__ unsigned smem_u32(const void* p){
    unsigned a;
    asm("{ .reg .u64 t; cvta.to.shared.u64 t, %1; cvt.u32.u64 %0, t; }" : "=r"(a) : "l"(p));
    return a;
}
__device__ __forceinline__ void cpa16(unsigned s, const void* g){
    asm volatile("cp.async.ca.shared.global [%0], [%1], 16;" :: "r"(s), "l"(g));
}

// ROWSx128 f32 -> smem tf32 (RNA), ld=LDA
template<int NT, int ROWS>
__device__ __forceinline__ void load_tile(unsigned* dst, const float* src, int srcStride,
                                          int tid){
    #pragma unroll
    for (int it = 0; it < ROWS*32/NT; ++it){
        int idx = tid + it*NT;
        int r = idx >> 5, c = (idx & 31) << 2;
        float4 v = *(const float4*)(src + (size_t)r*srcStride + c);
        uint4 u = make_uint4(f2tf32(v.x), f2tf32(v.y), f2tf32(v.z), f2tf32(v.w));
        *(uint4*)(dst + r*LDA + c) = u;
    }
}

// ---------------- mask -> bitmask ----------------
__global__ __launch_bounds__(256) void prep_mask(const int* __restrict__ mask)
{
    size_t o = (size_t)blockIdx.x * 256 + threadIdx.x;
    const int* p = mask + o*32;
    unsigned bits = 0;
    #pragma unroll
    for (int i = 0; i < 32; i += 4){
        int4 v = *(const int4*)(p + i);
        bits |= ((unsigned)(v.x & 1) << i)     | ((unsigned)(v.y & 1) << (i+1))
              | ((unsigned)(v.z & 1) << (i+2)) | ((unsigned)(v.w & 1) << (i+3));
    }
    g_MBITS[o] = bits;
}

// ---------------- QKV projection -> half outputs ----------------
__global__ __launch_bounds__(256) void proj_tc(const float* __restrict__ X,
                                               const float* __restrict__ W,
                                               const float* __restrict__ bias, int which)
{
    extern __shared__ unsigned sm[];
    unsigned* As = sm;
    unsigned* Bs = sm + 128*LDA;
    const int tid = threadIdx.x, lane = tid & 31, g = lane >> 2, t4 = lane & 3, w = tid >> 5;
    const int m0w = (w & 3) * 32, n0w = (w >> 2) * 64;
    const int m0 = blockIdx.y * 128, n0 = blockIdx.x * 128;

    load_tile<256,128>(As, X + (size_t)m0*Dh, Dh, tid);
    load_tile<256,128>(Bs, W + (size_t)n0*Dh, Dh, tid);
    __syncthreads();

    float acc[2][8][4] = {};
    #pragma unroll 4
    for (int kk = 0; kk < 16; ++kk){
        unsigned a[2][4];
        #pragma unroll
        for (int mi = 0; mi < 2; ++mi){
            const unsigned* p = As + (m0w + mi*16 + g)*LDA + kk*8 + t4;
            a[mi][0] = p[0];       a[mi][2] = p[4];
            a[mi][1] = p[8*LDA];   a[mi][3] = p[8*LDA + 4];
        }
        #pragma unroll
        for (int j = 0; j < 8; ++j){
            const unsigned* p = Bs + (n0w + j*8 + g)*LDA + kk*8 + t4;
            mma8(acc[0][j], a[0], p[0], p[4]);
            mma8(acc[1][j], a[1], p[0], p[4]);
        }
    }

    const int b = m0 >> 11, sbase = m0 & 2047, h = n0 >> 7;
    const size_t bh = (size_t)(b*NHEAD + h);
    #pragma unroll
    for (int mi = 0; mi < 2; ++mi)
        #pragma unroll
        for (int half_ = 0; half_ < 2; ++half_){
            int rl = m0w + mi*16 + half_*8 + g;
            int s = sbase + rl;
            #pragma unroll
            for (int j = 0; j < 8; ++j){
                int d = n0w + j*8 + 2*t4;
                float v0 = acc[mi][j][half_*2]   + bias[n0 + d];
                float v1 = acc[mi][j][half_*2+1] + bias[n0 + d + 1];
                if (which == 0){
                    unsigned hv = pack_h2(v0*QSCALE, v1*QSCALE);
                    *(unsigned*)(g_Qh + (bh*SEQ + s)*Dh + d) = hv;
                } else if (which == 1){
                    unsigned hv = pack_h2(v0, v1);
                    *(unsigned*)(g_Kh + (bh*SEQ + s)*Dh + d) = hv;
                } else {
                    g_VTh[(bh*Dh + d)*SEQ + s]     = __float2half_rn(v0);
                    g_VTh[(bh*Dh + d + 1)*SEQ + s] = __float2half_rn(v1);
                }
            }
        }
}

// ---------------- fused attention: fp16 mma, 64 q-rows/CTA, 2 CTAs/SM ----------------
__global__ __launch_bounds__(128, 2) void attn_mma(float* __restrict__ weights)
{
    extern __shared__ unsigned sm[];
    unsigned* Qs = sm;
    __shared__ float lpart[64][2];
    __shared__ float linvs[64];

    const int tid = threadIdx.x, lane = tid & 31, g = lane >> 2, t4 = lane & 3, w = tid >> 5;
    const int m0w = (w & 1) * 32;
    const int wn  = w >> 1;
    const int n0s = wn * 32;
    const int n0d = wn * 64;
    const int h = blockIdx.x, q0 = blockIdx.y * 64, b = blockIdx.z;
    const size_t bh = (size_t)(b*NHEAD + h);
    const __half* Qg  = g_Qh  + bh*SEQ*Dh + (size_t)q0*Dh;
    const __half* Kg  = g_Kh  + bh*SEQ*Dh;
    const __half* VTg = g_VTh + bh*SEQ*Dh;          // [d][s]
    const unsigned* mbits = g_MBITS + (size_t)b*SEQ*(SEQ/32);
    float* wb = weights + bh*(size_t)SEQ*SEQ;

    const unsigned smb = smem_u32(sm);
    const unsigned kb_u[2] = { smb + OFF_KB0*4u, smb + OFF_KB1*4u };
    const unsigned vb_u[2] = { smb + OFF_VB0*4u, smb + OFF_VB1*4u };

    // prologue: Q + K0 + V0 via cp.async (halves)
    #pragma unroll
    for (int i = 0; i < 8; ++i){
        int idx = tid + i*128;
        int r = idx >> 4, c = idx & 15;
        cpa16(smb + (unsigned)(r*LQW + c*4)*4u, Qg + (size_t)r*Dh + c*8);       // Q
        cpa16(kb_u[0] + (unsigned)(r*LQW + c*4)*4u, Kg + (size_t)r*Dh + c*8);   // K0
        int rv = idx >> 3, cv = idx & 7;
        cpa16(vb_u[0] + (unsigned)(rv*LVW + cv*4)*4u, VTg + (size_t)rv*SEQ + cv*8); // V0
    }
    asm volatile("cp.async.commit_group;");

    float lsum[2][2] = {{0.f,0.f},{0.f,0.f}};
    float ctx[2][8][4] = {};

    for (int it = 0; it < 32; ++it){
        const int t0 = it * 64;
        const int cur = it & 1, nxt = cur ^ 1;
        if (it + 1 < 32){
            const __half* Kn  = Kg  + (size_t)(t0 + 64)*Dh;
            const __half* VTn = VTg + (t0 + 64);
            #pragma unroll
            for (int i = 0; i < 8; ++i){
                int idx = tid + i*128;
                int r = idx >> 4, c = idx & 15;
                cpa16(kb_u[nxt] + (unsigned)(r*LQW + c*4)*4u, Kn + (size_t)r*Dh + c*8);
                int rv = idx >> 3, cv = idx & 7;
                cpa16(vb_u[nxt] + (unsigned)(rv*LVW + cv*4)*4u, VTn + (size_t)rv*SEQ + cv*8);
            }
            asm volatile("cp.async.commit_group;");
            asm volatile("cp.async.wait_group 1;");
        } else {
            asm volatile("cp.async.wait_group 0;");
        }
        __syncthreads();

        const unsigned* Ks = sm + (cur ? OFF_KB1 : OFF_KB0);
        const unsigned* Vs = sm + (cur ? OFF_VB1 : OFF_VB0);
        unsigned*       Ws = sm + (cur ? OFF_KB1 : OFF_KB0);   // alias after QK

        // ---- QK: fp16 k16, 8 k-steps; warp 32x32 ----
        float acc[2][4][4] = {};
        #pragma unroll
        for (int kk = 0; kk < 8; ++kk){
            unsigned a[2][4];
            #pragma unroll
            for (int mi = 0; mi < 2; ++mi){
                const unsigned* p = Qs + (m0w + mi*16 + g)*LQW + kk*8 + t4;
                a[mi][0] = p[0];       a[mi][2] = p[4];
                a[mi][1] = p[8*LQW];   a[mi][3] = p[8*LQW + 4];
            }
            #pragma unroll
            for (int j = 0; j < 4; ++j){
                const unsigned* p = Ks + (n0s + j*8 + g)*LQW + kk*8 + t4;
                mma16h(acc[0][j], a[0], p[0], p[4]);
                mma16h(acc[1][j], a[1], p[0], p[4]);
            }
        }
        __syncthreads();

        // ---- epilogue: u = masked ? 0 : ex2(s); STG u (f32); STS u (f16) ----
        #pragma unroll
        for (int mi = 0; mi < 2; ++mi){
            const int rl0 = m0w + mi*16 + g;
            const int r0  = q0 + rl0;
            const int wword = (t0 + n0s) >> 5;
            const unsigned mb0 = mbits[(size_t)r0*(SEQ/32) + wword];
            const unsigned mb1 = mbits[(size_t)(r0+8)*(SEQ/32) + wword];
            float* wr0 = wb + (size_t)r0*SEQ + t0;
            float* wr1 = wr0 + 8*SEQ;
            #pragma unroll
            for (int j = 0; j < 4; ++j){
                int cc = n0s + j*8 + 2*t4;
                int sh = j*8 + 2*t4;
                float u00 = ((mb0 >> sh) & 1u)     ? 0.f : ex2f(acc[mi][j][0]);
                float u01 = ((mb0 >> (sh+1)) & 1u) ? 0.f : ex2f(acc[mi][j][1]);
                float u10 = ((mb1 >> sh) & 1u)     ? 0.f : ex2f(acc[mi][j][2]);
                float u11 = ((mb1 >> (sh+1)) & 1u) ? 0.f : ex2f(acc[mi][j][3]);
                *(float2*)(wr0 + cc) = make_float2(u00, u01);
                *(float2*)(wr1 + cc) = make_float2(u10, u11);
                lsum[mi][0] += u00 + u01;
                lsum[mi][1] += u10 + u11;
                Ws[rl0*LVW + (n0s >> 1) + 4*j + t4]       = pack_h2(u00, u01);
                Ws[(rl0 + 8)*LVW + (n0s >> 1) + 4*j + t4] = pack_h2(u10, u11);
            }
        }
        __syncthreads();

        // ---- PV: fp16 k16, 4 k-steps; w(64x64) @ V(64x128) ----
        #pragma unroll
        for (int kk = 0; kk < 4; ++kk){
            unsigned a[2][4];
            #pragma unroll
            for (int mi = 0; mi < 2; ++mi){
                const unsigned* p = Ws + (m0w + mi*16 + g)*LVW + kk*8 + t4;
                a[mi][0] = p[0];       a[mi][2] = p[4];
                a[mi][1] = p[8*LVW];   a[mi][3] = p[8*LVW + 4];
            }
            #pragma unroll
            for (int j = 0; j < 8; ++j){
                const unsigned* p = Vs + (n0d + j*8 + g)*LVW + kk*8 + t4;
                mma16h(ctx[0][j], a[0], p[0], p[4]);
                mma16h(ctx[1][j], a[1], p[0], p[4]);
            }
        }
        __syncthreads();
    }

    // ---- reduce l ----
    #pragma unroll
    for (int mi = 0; mi < 2; ++mi)
        #pragma unroll
        for (int half_ = 0; half_ < 2; ++half_){
            float v = lsum[mi][half_];
            v += __shfl_xor_sync(0xffffffffu, v, 1);
            v += __shfl_xor_sync(0xffffffffu, v, 2);
            if (t4 == 0) lpart[m0w + mi*16 + half_*8 + g][wn] = v;
        }
    __syncthreads();
    if (tid < 64){
        float li = 1.0f / (lpart[tid][0] + lpart[tid][1]);
        linvs[tid] = li;
        g_LINV[bh*SEQ + q0 + tid] = li;
    }
    __syncthreads();

    // ---- ctx * linv -> g_CTX ----
    float* Cb = g_CTX + (bh*SEQ + (size_t)q0)*Dh;
    #pragma unroll
    for (int mi = 0; mi < 2; ++mi)
        #pragma unroll
        for (int half_ = 0; half_ < 2; ++half_){
            int rl = m0w + mi*16 + half_*8 + g;
            float li = linvs[rl];
            #pragma unroll
            for (int j = 0; j < 8; ++j){
                int d = n0d + j*8 + 2*t4;
                *(float2*)(Cb + (size_t)rl*Dh + d) =
                    make_float2(ctx[mi][j][half_*2]*li, ctx[mi][j][half_*2+1]*li);
            }
        }
}

// ---------------- weights row-normalize ----------------
__global__ __launch_bounds__(256) void norm_w(float* __restrict__ weights)
{
    const float li = g_LINV[blockIdx.x];
    float4* row = (float4*)(weights + (size_t)blockIdx.x * SEQ);
    int t = threadIdx.x;
    float4 a = row[t], c = row[t + 256];
    a.x*=li; a.y*=li; a.z*=li; a.w*=li;
    c.x*=li; c.y*=li; c.z*=li; c.w*=li;
    row[t] = a; row[t + 256] = c;
}

// ---------------- output projection (tf32) ----------------
__global__ __launch_bounds__(256) void outproj_tc(const float* __restrict__ Wd,
                                                  const float* __restrict__ bd,
                                                  float* __restrict__ out)
{
    extern __shared__ unsigned sm[];
    unsigned* As = sm;              // 64 x LDA
    unsigned* Bs = sm + 64*LDA;     // 128 x LDA
    const int tid = threadIdx.x, lane = tid & 31, g = lane >> 2, t4 = lane & 3, w = tid >> 5;
    const int m0w = (w & 3) * 16, n0w = (w >> 2) * 64;
    const int m0 = blockIdx.x * 64;
    const int b = m0 >> 11, sbase = m0 & 2047;

    float acc[8][4] = {};
    for (int kt = 0; kt < NHEAD; ++kt){
        __syncthreads();
        load_tile<256,64>(As, g_CTX + (((size_t)(b*NHEAD + kt))*SEQ + sbase)*Dh, Dh, tid);
        load_tile<256,128>(Bs, Wd + (size_t)kt*Dh, NHD, tid);
        __syncthreads();
        #pragma unroll 4
        for (int kk = 0; kk < 16; ++kk){
            unsigned a[4];
            const unsigned* pa = As + (m0w + g)*LDA + kk*8 + t4;
            a[0] = pa[0];       a[2] = pa[4];
            a[1] = pa[8*LDA];   a[3] = pa[8*LDA + 4];
            #pragma unroll
            for (int j = 0; j < 8; ++j){
                const unsigned* p = Bs + (n0w + j*8 + g)*LDA + kk*8 + t4;
                mma8(acc[j], a, p[0], p[4]);
            }
        }
    }
    #pragma unroll
    for (int half_ = 0; half_ < 2; ++half_){
        int rl = m0w + half_*8 + g;
        float* Or = out + (size_t)(m0 + rl)*Dh;
        #pragma unroll
        for (int j = 0; j < 8; ++j){
            int d = n0w + j*8 + 2*t4;
            *(float2*)(Or + d) = make_float2(acc[j][half_*2]   + bd[d],
                                             acc[j][half_*2+1] + bd[d + 1]);
        }
    }
}

// ---------------------------------------------------------------------------
extern "C" void kernel_launch(void* const* d_in, const int* in_sizes, int n_in,
                              void* d_out, int out_size)
{
    (void)in_sizes; (void)n_in; (void)out_size;
    const float* x    = (const float*)d_in[0];
    const int*   mask = (const int*)  d_in[1];
    const float* Wq   = (const float*)d_in[2];
    const float* bq   = (const float*)d_in[3];
    const float* Wk   = (const float*)d_in[4];
    const float* bk   = (const float*)d_in[5];
    const float* Wv   = (const float*)d_in[6];
    const float* bv   = (const float*)d_in[7];
    const float* Wd   = (const float*)d_in[8];
    const float* bd   = (const float*)d_in[9];

    float* out     = (float*)d_out;
    float* weights = out + (size_t)NB*SEQ*Dh;

    const size_t smem_proj = (size_t)2*128*LDA*4;          // 135168
    const size_t smem_attn = SMEM_ATTN;                    // 89088
    const size_t smem_outp = (size_t)(64*LDA + 128*LDA)*4; // 101376

    cudaFuncSetAttribute(proj_tc,    cudaFuncAttributeMaxDynamicSharedMemorySize, (int)smem_proj);
    cudaFuncSetAttribute(attn_mma,   cudaFuncAttributeMaxDynamicSharedMemorySize, (int)smem_attn);
    cudaFuncSetAttribute(outproj_tc, cudaFuncAttributeMaxDynamicSharedMemorySize, (int)smem_outp);

    prep_mask<<<NB*SEQ*(SEQ/32)/256, 256>>>(mask);

    dim3 g1(NHD/128, MROWS/128);            // (16, 32)
    proj_tc<<<g1, 256, smem_proj>>>(x, Wq, bq, 0);
    proj_tc<<<g1, 256, smem_proj>>>(x, Wk, bk, 1);
    proj_tc<<<g1, 256, smem_proj>>>(x, Wv, bv, 2);

    dim3 g2(NHEAD, SEQ/64, NB);             // (16, 32, 2), 2 CTAs/SM
    attn_mma<<<g2, 128, smem_attn>>>(weights);

    norm_w<<<NB*NHEAD*SEQ, 256>>>(weights);

    outproj_tc<<<MROWS/64, 256, smem_outp>>>(Wd, bd, out);
}